// round 13
// baseline (speedup 1.0000x reference)
#include <cuda_runtime.h>
#include <cuda_bf16.h>
#include <cstdint>

#define BATCH    128
#define WTOT     8192
#define DDIM     64
#define SSPLIT   4
#define WSEG     (WTOT / SSPLIT)     // 2048
#define WC       128                 // w per staged tile
#define NTILES   (WSEG / WC)         // 16
#define NTHREADS 512
#define KSTEPS   4                   // 128 w / k32 per mma

// Scratch partials (no allocations allowed)
__device__ float g_part[BATCH][SSPLIT][DDIM * DDIM];   // upper 16x16 blocks only
__device__ float s_part[BATCH][SSPLIT][DDIM];
__device__ unsigned int done_cnt[BATCH];               // zero-init; reset by finalizer

__device__ __forceinline__ uint32_t smem_u32(const void* p) {
    uint32_t a;
    asm("{ .reg .u64 t; cvta.to.shared.u64 t, %1; cvt.u32.u64 %0, t; }" : "=r"(a) : "l"(p));
    return a;
}
__device__ __forceinline__ unsigned short cvt8(float hi, float lo) {
    unsigned short h;
    asm("cvt.rn.satfinite.e4m3x2.f32 %0, %1, %2;" : "=h"(h) : "f"(hi), "f"(lo));
    return h;
}
__device__ __forceinline__ uint32_t pack16(unsigned short lo, unsigned short hi) {
    uint32_t r; asm("mov.b32 %0, {%1, %2};" : "=r"(r) : "h"(lo), "h"(hi)); return r;
}
__device__ __forceinline__ void sts32(uint32_t addr, uint32_t r0) {
    asm volatile("st.shared.b32 [%0], %1;" :: "r"(addr), "r"(r0) : "memory");
}
__device__ __forceinline__ uint32_t lds32(uint32_t addr) {
    uint32_t r; asm volatile("ld.shared.b32 %0, [%1];" : "=r"(r) : "r"(addr)); return r;
}
__device__ __forceinline__ void mma_fp8(float* d,
                                        uint32_t a0, uint32_t a1, uint32_t a2, uint32_t a3,
                                        uint32_t b0, uint32_t b1) {
    asm volatile(
        "mma.sync.aligned.m16n8k32.row.col.f32.e4m3.e4m3.f32 "
        "{%0,%1,%2,%3}, {%4,%5,%6,%7}, {%8,%9}, {%0,%1,%2,%3};"
        : "+f"(d[0]), "+f"(d[1]), "+f"(d[2]), "+f"(d[3])
        : "r"(a0), "r"(a1), "r"(a2), "r"(a3), "r"(b0), "r"(b1));
}

// fp8 stage: [d][w], 128 B per row. Byte-space XOR swizzle (4B-granular):
//   bank = (w>>2) ^ ( (d&7)<<2 | (d>>3)&3 ) ^ bit3(d>>5)  -> STS & LDS conflict-free.
#define XSW(d) (((((d) & 7) << 4) | ((((d) >> 3) & 3) << 2)) ^ ((d) & 32))

__global__ __launch_bounds__(NTHREADS, 2)
void gram_kernel(const float* __restrict__ x, float* __restrict__ out) {
    __shared__ __align__(16) uint8_t stage[2][DDIM * WC];  // 2 x 8 KB fp8 tiles
    __shared__ float4 sums[NTHREADS];                       // 8 KB
    __shared__ unsigned int lastflag;

    const int tid  = threadIdx.x;
    const int wid  = tid >> 5;
    const int lane = tid & 31;
    const int s = blockIdx.x;
    const int b = blockIdx.y;

    const uint32_t stg = smem_u32(&stage[0][0]);

    // Phase A role: thread owns 4x4 block: features 4*(tid&15)+j, w = 4*(tid>>4)+i
    const int dq = tid & 15;
    const int wq = tid >> 4;                 // 0..31
    const uint32_t wb = (uint32_t)(4 * wq);  // byte offset of this thread's w-quad

    // ---- warp -> ONE upper-triangular 16x16 block ----
    int rA, cAb;
    if (wid < 4)      { rA = wid; cAb = wid;     }
    else if (wid < 7) { rA = 0;   cAb = wid - 3; }
    else if (wid < 9) { rA = 1;   cAb = wid - 5; }
    else              { rA = 2;   cAb = 3;       }
    const bool active = (wid < 10);

    // per-lane fragment addressing constants
    const uint32_t wl = (uint32_t)(4 * (lane & 3));
    const int r0 = 16 * rA + (lane >> 2);
    const int r1 = r0 + 8;
    const int n0 = 16 * cAb + (lane >> 2);
    const int n1 = n0 + 8;
    const uint32_t RA0 = (uint32_t)(128 * r0), XA0 = XSW(r0);
    const uint32_t RA1 = (uint32_t)(128 * r1), XA1 = XSW(r1);
    const uint32_t RB0 = (uint32_t)(128 * n0), XB0 = XSW(n0);
    const uint32_t RB1 = (uint32_t)(128 * n1), XB1 = XSW(n1);

    const float4* gp = (const float4*)(x + ((long)b * WTOT + (long)s * WSEG) * DDIM);

    float acc[2][4];
#pragma unroll
    for (int t = 0; t < 2; t++)
#pragma unroll
        for (int r = 0; r < 4; r++) acc[t][r] = 0.f;

    float sum0 = 0.f, sum1 = 0.f, sum2 = 0.f, sum3 = 0.f;

    // chunk index (float4 units): 64*wq + 16*i + dq  <=> (w = 4wq+i, feature-quad dq)
    float4 v[4];
#pragma unroll
    for (int i = 0; i < 4; i++) v[i] = gp[64 * wq + 16 * i + dq];

#pragma unroll 1
    for (int c = 0; c < NTILES; c++) {
        const uint32_t sbase = stg + (uint32_t)((c & 1) * (DDIM * WC));

        // ---- Phase A: scale x16, cvt fp32->e4m3, packed STS.32, column sums ----
        const float* vf = (const float*)v;
#pragma unroll
        for (int j = 0; j < 4; j++) {
            float f0 = vf[0 + j], f1 = vf[4 + j], f2 = vf[8 + j], f3 = vf[12 + j];
            unsigned short h0 = cvt8(16.f * f1, 16.f * f0);
            unsigned short h1 = cvt8(16.f * f3, 16.f * f2);
            const int d = 4 * dq + j;
            sts32(sbase + (uint32_t)(128 * d) + (wb ^ (uint32_t)XSW(d)), pack16(h0, h1));
        }
        sum0 += v[0].x + v[1].x + v[2].x + v[3].x;
        sum1 += v[0].y + v[1].y + v[2].y + v[3].y;
        sum2 += v[0].z + v[1].z + v[2].z + v[3].z;
        sum3 += v[0].w + v[1].w + v[2].w + v[3].w;

        // prefetch next tile BEFORE the barrier (max latency hiding)
        if (c + 1 < NTILES) {
#pragma unroll
            for (int i = 0; i < 4; i++)
                v[i] = gp[(c + 1) * 2048 + 64 * wq + 16 * i + dq];
        }
        __syncthreads();

        // ---- MMA: one upper-tri 16x16 block per warp, fp8 k32, LDS.32 fragments ----
        if (active) {
#pragma unroll
            for (int ks = 0; ks < KSTEPS; ks++) {
                const uint32_t w0 = (uint32_t)(32 * ks) + wl;   // no carry: bits disjoint
                uint32_t a0 = lds32(sbase + RA0 + (w0 ^ XA0));
                uint32_t a1 = lds32(sbase + RA1 + (w0 ^ XA1));
                uint32_t a2 = lds32(sbase + RA0 + ((w0 + 16) ^ XA0));
                uint32_t a3 = lds32(sbase + RA1 + ((w0 + 16) ^ XA1));
                uint32_t b0 = lds32(sbase + RB0 + (w0 ^ XB0));
                uint32_t b1 = lds32(sbase + RB0 + ((w0 + 16) ^ XB0));
                uint32_t b2 = lds32(sbase + RB1 + (w0 ^ XB1));
                uint32_t b3 = lds32(sbase + RB1 + ((w0 + 16) ^ XB1));
                mma_fp8(acc[0], a0, a1, a2, a3, b0, b1);
                mma_fp8(acc[1], a0, a1, a2, a3, b2, b3);
            }
        }
        // MMA(c) reads consumed into regs before sync(c+1); phase A(c+2) reuses buffer after.
    }

    // ---- write Gram partial block (upper triangle only; scaled by 256) ----
    if (active) {
        const int g = lane >> 2;
        const int col2 = 2 * (lane & 3);
        float* gpart = &g_part[b][s][0];
#pragma unroll
        for (int t = 0; t < 2; t++) {
            const int jcol = 16 * cAb + 8 * t + col2;
            *(float2*)&gpart[(16 * rA + g) * DDIM + jcol]     = make_float2(acc[t][0], acc[t][1]);
            *(float2*)&gpart[(16 * rA + g + 8) * DDIM + jcol] = make_float2(acc[t][2], acc[t][3]);
        }
    }

    // ---- column sums -> s_part (exact fp32) ----
    {
        const int q = tid & 15, p = tid >> 4;
        sums[(q << 5) | p] = make_float4(sum0, sum1, sum2, sum3);
    }
    __syncthreads();
    if (tid < DDIM) {
        const int q = tid >> 2, r = tid & 3;
        const float* sp = (const float*)sums;
        float a = 0.f;
#pragma unroll
        for (int p = 0; p < 32; p++) a += sp[(((q << 5) | p) << 2) + r];
        s_part[b][s][tid] = a;
    }

    // ---- arrival protocol: last CTA of this batch finalizes ----
    __threadfence();
    __syncthreads();
    if (tid == 0) {
        unsigned int old = atomicAdd(&done_cnt[b], 1u);
        lastflag = (old == SSPLIT - 1);
        if (lastflag) done_cnt[b] = 0;   // reset for next graph replay
    }
    __syncthreads();
    if (!lastflag) return;
    __threadfence();   // acquire: make peers' partials visible

    // ================= inline finalize (smem reuse) =================
    float* cov  = (float*)&stage[0][0];          // 16 KB
    float* ssum = (float*)&sums[0];              // 64 floats
    float* stdv = ssum + DDIM;                   // 64 floats

    const float gsc = 1.0f / 256.0f;             // undo x16*x16 fp8 scaling
    for (int idx = tid; idx < DDIM * DDIM; idx += NTHREADS) {
        const int i = idx >> 6, j = idx & 63;
        const int src = ((i >> 4) <= (j >> 4)) ? idx : (j * DDIM + i);  // mirror lower
        float a = 0.f;
#pragma unroll
        for (int ss = 0; ss < SSPLIT; ss++) a += __ldcg(&g_part[b][ss][src]);
        cov[idx] = a * gsc;
    }
    __syncthreads();   // sums smem repurposed below
    if (tid < DDIM) {
        float a = 0.f;
#pragma unroll
        for (int ss = 0; ss < SSPLIT; ss++) a += __ldcg(&s_part[b][ss][tid]);
        ssum[tid] = a;
    }
    __syncthreads();

    const float invW  = 1.0f / (float)WTOT;
    const float invW1 = 1.0f / (float)(WTOT - 1);

    if (tid < DDIM) {
        float Si = ssum[tid];
        float cc = (cov[tid * DDIM + tid] - Si * Si * invW) * invW1;
        stdv[tid] = sqrtf(cc) + 1e-8f;
    }
    __syncthreads();

    if (tid < DDIM) {
        const int i = tid;
        float Si = ssum[i];
        float inv_si = 1.0f / stdv[i];
        float cnt = 0.f;
#pragma unroll 8
        for (int j = 0; j < DDIM; j++) {
            float cc = (cov[i * DDIM + j] - Si * ssum[j] * invW) * invW1;
            float corr = cc * inv_si / stdv[j];
            if (fabsf(corr) > 0.3f) cnt += 1.0f;
        }
        out[b * DDIM + i] = cnt - 1.0f;
    }
}

extern "C" void kernel_launch(void* const* d_in, const int* in_sizes, int n_in,
                              void* d_out, int out_size) {
    const float* x = (const float*)d_in[0];
    float* out = (float*)d_out;

    dim3 grid(SSPLIT, BATCH);
    gram_kernel<<<grid, NTHREADS>>>(x, out);
}

// round 14
// speedup vs baseline: 1.0916x; 1.0916x over previous
#include <cuda_runtime.h>
#include <cuda_bf16.h>
#include <cstdint>

#define BATCH    128
#define WTOT     8192
#define DDIM     64
#define SSPLIT   4
#define WSEG     (WTOT / SSPLIT)     // 2048
#define WC       128                 // w per staged tile
#define NTILES   (WSEG / WC)         // 16
#define NTHREADS 512
#define KSTEPS   8                   // 128 w / k16 per mma

// Scratch partials (no allocations allowed)
__device__ float g_part[BATCH][SSPLIT][DDIM * DDIM];   // upper 16x16 blocks only
__device__ float s_part[BATCH][SSPLIT][DDIM];
__device__ unsigned int done_cnt[BATCH];               // zero-init; reset by finalizer

__device__ __forceinline__ uint32_t smem_u32(const void* p) {
    uint32_t a;
    asm("{ .reg .u64 t; cvta.to.shared.u64 t, %1; cvt.u32.u64 %0, t; }" : "=r"(a) : "l"(p));
    return a;
}
__device__ __forceinline__ uint32_t cvt2(float hi, float lo) {
    uint32_t r; asm("cvt.rn.bf16x2.f32 %0, %1, %2;" : "=r"(r) : "f"(hi), "f"(lo)); return r;
}
__device__ __forceinline__ void sts64(uint32_t addr, uint32_t r0, uint32_t r1) {
    asm volatile("st.shared.v2.b32 [%0], {%1, %2};" :: "r"(addr), "r"(r0), "r"(r1) : "memory");
}
__device__ __forceinline__ void ldsm4t(uint32_t& r0, uint32_t& r1, uint32_t& r2, uint32_t& r3,
                                       uint32_t addr) {
    asm volatile("ldmatrix.sync.aligned.m8n8.x4.trans.shared.b16 {%0,%1,%2,%3}, [%4];"
                 : "=r"(r0), "=r"(r1), "=r"(r2), "=r"(r3) : "r"(addr));
}
__device__ __forceinline__ void mma16816(float* d,
                                         uint32_t a0, uint32_t a1, uint32_t a2, uint32_t a3,
                                         uint32_t b0, uint32_t b1) {
    asm volatile(
        "mma.sync.aligned.m16n8k16.row.col.f32.bf16.bf16.f32 "
        "{%0,%1,%2,%3}, {%4,%5,%6,%7}, {%8,%9}, {%0,%1,%2,%3};"
        : "+f"(d[0]), "+f"(d[1]), "+f"(d[2]), "+f"(d[3])
        : "r"(a0), "r"(a1), "r"(a2), "r"(a3), "r"(b0), "r"(b1));
}

// bf16 mma tile: [w][d], 128 B per row, XOR-swizzled by ((w&7)<<4).
#define SWZ(w, d2bytes) ((uint32_t)((w) * 128 + (d2bytes)) ^ (((uint32_t)(w) & 7u) << 4))

__global__ __launch_bounds__(NTHREADS, 2)
void gram_kernel(const float* __restrict__ x, float* __restrict__ out) {
    __shared__ __align__(16) uint8_t stage[2][WC * 128];   // 32 KB double-buffered
    __shared__ float4 sums[NTHREADS];                       // 8 KB
    __shared__ unsigned int lastflag;

    const int tid  = threadIdx.x;
    const int wid  = tid >> 5;
    const int lane = tid & 31;
    const int s = blockIdx.x;
    const int b = blockIdx.y;

    const uint32_t stg = smem_u32(&stage[0][0]);

    // Phase A role: chunk f = tid + 512*i -> w = f>>4 (w0 + 32*i), d-quad = tid&15
    const int d0 = 4 * (tid & 15);
    const int w0 = tid >> 4;                 // 0..31

    // ---- warp -> ONE upper-triangular 16x16 block ----
    int rA, cAb;
    if (wid < 4)      { rA = wid; cAb = wid;     }
    else if (wid < 7) { rA = 0;   cAb = wid - 3; }
    else if (wid < 9) { rA = 1;   cAb = wid - 5; }
    else              { rA = 2;   cAb = 3;       }
    const bool active = (wid < 10);

    const int kA = (lane & 7) + ((lane & 16) >> 1);
    const int kB = (lane & 7) + (lane & 8);
    const uint32_t swx = ((uint32_t)lane & 7u) << 4;
    const uint32_t oA1 = (uint32_t)(kA * 128 + (16 * rA + (lane & 8)) * 2) ^ swx;
    const uint32_t oB1 = (uint32_t)(kB * 128 + (16 * cAb + ((lane & 16) >> 1)) * 2) ^ swx;

    const float4* gp = (const float4*)(x + ((long)b * WTOT + (long)s * WSEG) * DDIM);

    float acc[2][4];
#pragma unroll
    for (int t = 0; t < 2; t++)
#pragma unroll
        for (int r = 0; r < 4; r++) acc[t][r] = 0.f;

    float sum0 = 0.f, sum1 = 0.f, sum2 = 0.f, sum3 = 0.f;

    float4 v[4];
#pragma unroll
    for (int i = 0; i < 4; i++) v[i] = gp[tid + 512 * i];

#pragma unroll 1
    for (int c = 0; c < NTILES; c++) {
        const uint32_t sbase = stg + (uint32_t)((c & 1) * (WC * 128));
        const bool more = (c + 1 < NTILES);
        const float4* gnext = gp + (c + 1) * 2048;

        // ---- Phase A: consume v[i] (cvt + sums + STS), then IMMEDIATELY
        //      re-issue the LDG for tile c+1 into v[i] so the load is in
        //      flight for the entire tile period (DRAM never idles). ----
#pragma unroll
        for (int i = 0; i < 4; i++) {
            uint32_t r0 = cvt2(v[i].y, v[i].x);
            uint32_t r1 = cvt2(v[i].w, v[i].z);
            sum0 += v[i].x; sum1 += v[i].y; sum2 += v[i].z; sum3 += v[i].w;
            const int w = w0 + 32 * i;
            sts64(sbase + SWZ(w, d0 * 2), r0, r1);
            if (more) v[i] = gnext[tid + 512 * i];   // WAR on v[i] resolved by scoreboard
        }
        __syncthreads();

        // ---- MMA: one upper-tri block per warp ----
        if (active) {
#pragma unroll
            for (int ks = 0; ks < KSTEPS; ks++) {
                const uint32_t kb = sbase + (uint32_t)(ks * 2048);
                uint32_t a0, a1, a2, a3, b0, b1, b2, b3;
                ldsm4t(a0, a1, a2, a3, kb + oA1);
                ldsm4t(b0, b1, b2, b3, kb + oB1);
                mma16816(acc[0], a0, a1, a2, a3, b0, b1);
                mma16816(acc[1], a0, a1, a2, a3, b2, b3);
            }
        }
        // MMA(c) ordered before phaseA(c+2) overwrite by sync(c+1).
    }

    // ---- write Gram partial block (upper triangle only) ----
    if (active) {
        const int g = lane >> 2;
        const int col2 = 2 * (lane & 3);
        float* gpart = &g_part[b][s][0];
#pragma unroll
        for (int t = 0; t < 2; t++) {
            const int jcol = 16 * cAb + 8 * t + col2;
            *(float2*)&gpart[(16 * rA + g) * DDIM + jcol]     = make_float2(acc[t][0], acc[t][1]);
            *(float2*)&gpart[(16 * rA + g + 8) * DDIM + jcol] = make_float2(acc[t][2], acc[t][3]);
        }
    }

    // ---- column sums -> s_part ----
    {
        const int q = tid & 15, p = tid >> 4;      // q: feature quad, p: 0..31
        sums[(q << 5) | p] = make_float4(sum0, sum1, sum2, sum3);
    }
    __syncthreads();
    if (tid < DDIM) {
        const int q = tid >> 2, r = tid & 3;
        const float* sp = (const float*)sums;
        float a = 0.f;
#pragma unroll
        for (int p = 0; p < 32; p++) a += sp[(((q << 5) | p) << 2) + r];
        s_part[b][s][tid] = a;
    }

    // ---- arrival protocol: last CTA of this batch finalizes ----
    __threadfence();
    __syncthreads();
    if (tid == 0) {
        unsigned int old = atomicAdd(&done_cnt[b], 1u);
        lastflag = (old == SSPLIT - 1);
        if (lastflag) done_cnt[b] = 0;   // reset for next graph replay
    }
    __syncthreads();
    if (!lastflag) return;
    __threadfence();   // acquire: make peers' partials visible

    // ================= inline finalize (smem reuse) =================
    float* cov  = (float*)&stage[0][0];          // 16 KB
    float* ssum = (float*)&sums[0];              // 64 floats
    float* stdv = ssum + DDIM;                   // 64 floats

    for (int idx = tid; idx < DDIM * DDIM; idx += NTHREADS) {
        const int i = idx >> 6, j = idx & 63;
        const int src = ((i >> 4) <= (j >> 4)) ? idx : (j * DDIM + i);  // mirror lower
        float a = 0.f;
#pragma unroll
        for (int ss = 0; ss < SSPLIT; ss++) a += __ldcg(&g_part[b][ss][src]);
        cov[idx] = a;
    }
    __syncthreads();   // sums smem is being repurposed below
    if (tid < DDIM) {
        float a = 0.f;
#pragma unroll
        for (int ss = 0; ss < SSPLIT; ss++) a += __ldcg(&s_part[b][ss][tid]);
        ssum[tid] = a;
    }
    __syncthreads();

    const float invW  = 1.0f / (float)WTOT;
    const float invW1 = 1.0f / (float)(WTOT - 1);

    if (tid < DDIM) {
        float Si = ssum[tid];
        float cc = (cov[tid * DDIM + tid] - Si * Si * invW) * invW1;
        stdv[tid] = sqrtf(cc) + 1e-8f;
    }
    __syncthreads();

    if (tid < DDIM) {
        const int i = tid;
        float Si = ssum[i];
        float inv_si = 1.0f / stdv[i];
        float cnt = 0.f;
#pragma unroll 8
        for (int j = 0; j < DDIM; j++) {
            float cc = (cov[i * DDIM + j] - Si * ssum[j] * invW) * invW1;
            float corr = cc * inv_si / stdv[j];
            if (fabsf(corr) > 0.3f) cnt += 1.0f;
        }
        out[b * DDIM + i] = cnt - 1.0f;
    }
}

extern "C" void kernel_launch(void* const* d_in, const int* in_sizes, int n_in,
                              void* d_out, int out_size) {
    const float* x = (const float*)d_in[0];
    float* out = (float*)d_out;

    dim3 grid(SSPLIT, BATCH);
    gram_kernel<<<grid, NTHREADS>>>(x, out);
}